// round 9
// baseline (speedup 1.0000x reference)
#include <cuda_runtime.h>
#include <math.h>

// Problem-fixed shapes
#define H   4096
#define W   4096
#define W2  8192

#define SCONST       1e-12f
#define EPS_V_FLOOR  (1e-32f / 6.0f)
#define PI_D         (3.14159265358979323846f / 1.1f)
#define PI_2         1.57079632679489662f

#define LANES_OUT 28                         // outputs per warp (2-lane halo each side)
#define WPB       8                          // warps per block
#define RPB       64                         // rows per block strip
#define NWC       ((W + LANES_OUT - 1) / LANES_OUT)  // 147 warp-columns
#define GX        ((NWC + WPB - 1) / WPB)    // 19
#define GY        (H / RPB)                  // 64
#define NBLK      (GX * GY)                  // 1216

__device__ double g_partials[NBLK];
__device__ unsigned int g_ticket;            // zero-init; reset by last block each call

// ---------------------------------------------------------------------------
// Math tail: derivatives -> penalty value. (Validated: rel_err == 0.0)
// ---------------------------------------------------------------------------
__device__ __forceinline__ float penalty_val(float ex, float ey,
                                             float exx, float exy, float eyy,
                                             float c) {
    const float exs = ex + SCONST;
    const float eys = ey + SCONST;
    const float x2 = exs * exs;
    const float y2 = eys * eys;
    const float ev2 = x2 + y2;
    const float rinv = rsqrtf(ev2);
    const float ev = fmaxf(ev2 * rinv, EPS_V_FLOOR);
    float num = fmaf(y2, exx, x2 * eyy);
    num = fmaf(-2.0f * (exs * eys), exy, num);
    const float rinv3 = (rinv * rinv) * rinv;
    const float kabs = fabsf(num) * rinv3;

    // |atan(ev/c)| = atan(ev/|c|), reflected so the poly arg is in [0,1].
    const float ac = fabsf(c);
    const float z = __fdividef(fminf(ev, ac), fmaxf(ev, ac));
    const float w = z * z;
    float p = fmaf(w, -0.0040540580f, 0.0218612288f);
    p = fmaf(w, p, -0.0559098861f);
    p = fmaf(w, p, 0.0964200441f);
    p = fmaf(w, p, -0.1390853351f);
    p = fmaf(w, p, 0.1994653599f);
    p = fmaf(w, p, -0.3332985605f);
    p = fmaf(w, p, 0.9999993329f);
    float t = z * p;
    t = (ev > ac) ? (PI_2 - t) : t;

    return fmaxf(fmaf(kabs, t, -PI_D), 0.0f);  // fmaxf(NaN,0)=0 == nansum drop
}

// ---------------------------------------------------------------------------
// Generic (boundary-exact) path: composed one-sided operators on the
// column-mirrored [H, 2W] field. Cold: <0.2% of elements.
// ---------------------------------------------------------------------------
__device__ __forceinline__ float Mld(const float* __restrict__ e, int i, int g) {
    int j = g < W ? g : (W2 - 1 - g);
    return __ldg(e + (size_t)i * W + j);
}

__device__ __noinline__ float generic_val(const float* __restrict__ e,
                                          int i, int j, float d) {
    const float rd = 1.0f / d;
    const float r2d = 0.5f / d;

    auto EXg = [&](int ii, int g) -> float {
        if (ii == 0)     return (Mld(e, 1, g) - Mld(e, 0, g)) * rd;
        if (ii == H - 1) return (Mld(e, H - 1, g) - Mld(e, H - 2, g)) * rd;
        return (Mld(e, ii + 1, g) - Mld(e, ii - 1, g)) * r2d;
    };
    auto EYg = [&](int ii, int g) -> float {
        if (g == 0) return (Mld(e, ii, 1) - Mld(e, ii, 0)) * rd;
        return (Mld(e, ii, g + 1) - Mld(e, ii, g - 1)) * r2d;
    };

    const float ex = EXg(i, j);
    const float ey = EYg(i, j);
    float exx, exy, eyy;
    if (i == 0)
        exx = (EXg(1, j) - EXg(0, j)) * rd;
    else if (i == H - 1)
        exx = (EXg(H - 1, j) - EXg(H - 2, j)) * rd;
    else
        exx = (EXg(i + 1, j) - EXg(i - 1, j)) * r2d;
    if (j == 0) {
        exy = (EXg(i, 1) - EXg(i, 0)) * rd;
        eyy = (EYg(i, 1) - EYg(i, 0)) * rd;
    } else {
        exy = (EXg(i, j + 1) - EXg(i, j - 1)) * r2d;
        eyy = (EYg(i, j + 1) - EYg(i, j - 1)) * r2d;
    }
    const float c = __ldg(e + (size_t)i * W + j);
    return penalty_val(ex, ey, exx, exy, eyy, c);
}

__device__ __forceinline__ float warp_reduce_f(float v) {
#pragma unroll
    for (int o = 16; o > 0; o >>= 1)
        v += __shfl_xor_sync(0xffffffffu, v, o);
    return v;
}

// ---------------------------------------------------------------------------
// Fused kernel: rolling-register column walk + shuffles for horizontal
// neighbors; 1 coalesced LDG per element; ticket-based final reduction.
// ---------------------------------------------------------------------------
__global__ __launch_bounds__(256, 6)
void curve_kernel(const float* __restrict__ eps, const float* __restrict__ gs,
                  float* __restrict__ out) {
    __shared__ double wpart[WPB];
    __shared__ double smr[256];
    __shared__ bool islast;

    const int lane = threadIdx.x & 31;
    const int warp = threadIdx.x >> 5;
    const int wc   = blockIdx.x * WPB + warp;       // warp-column index
    const int j    = wc * LANES_OUT + lane - 2;     // this lane's column
    const int t0   = blockIdx.y * RPB;

    const float d    = __ldg(gs);
    const float r2d  = 0.5f / d;
    const float r2d2 = r2d * r2d;

    const bool outlane = (lane >= 2) & (lane <= 29) & (j < W);
    const bool jfast   = (j >= 2) & (j <= W - 3);

    const int jl = min(max(j, 0), W - 1);           // load-column clamp (halo lanes)
    const float* pc = eps + jl;

    // Preload window rows t0-2..t0+1 (row-clamped; clamped rows only feed
    // outputs that the generic path overrides).
    float a0 = __ldg(pc + (size_t)max(t0 - 2, 0) * W);
    float a1 = __ldg(pc + (size_t)max(t0 - 1, 0) * W);
    float a2 = __ldg(pc + (size_t)t0 * W);
    float a3 = __ldg(pc + (size_t)(t0 + 1) * W);

    float acc = 0.0f;

#pragma unroll 4
    for (int t = t0; t < t0 + RPB; ++t) {
        const int rr = min(t + 2, H - 1);
        const float a4 = __ldg(pc + (size_t)rr * W);

        const float v = a3 - a1;                    // vertical diff at own column
        const unsigned m = 0xffffffffu;
        const float eyp  = __shfl_down_sync(m, a2, 1);
        const float eym  = __shfl_up_sync(m, a2, 1);
        const float ey2p = __shfl_down_sync(m, a2, 2);
        const float ey2m = __shfl_up_sync(m, a2, 2);
        const float vp   = __shfl_down_sync(m, v, 1);
        const float vm   = __shfl_up_sync(m, v, 1);

        const float ex  = v * r2d;
        const float ey  = (eyp - eym) * r2d;
        const float exx = (fmaf(-2.0f, a2, a4) + a0) * r2d2;
        const float eyy = (fmaf(-2.0f, a2, ey2p) + ey2m) * r2d2;
        const float exy = (vp - vm) * r2d2;
        const float fv  = penalty_val(ex, ey, exx, exy, eyy, a2);

        const bool rfast = (t >= 2) & (t <= H - 3);
        if (outlane) {
            if (jfast & rfast) acc += fv;
            else               acc += generic_val(eps, t, j, d);
        }

        a0 = a1; a1 = a2; a2 = a3; a3 = a4;         // renamed by unroll
    }

    // Block reduction
    const float ws = warp_reduce_f(acc);
    if (lane == 0) wpart[warp] = (double)ws;
    __syncthreads();
    if (threadIdx.x == 0) {
        double s = 0.0;
#pragma unroll
        for (int w = 0; w < WPB; w++) s += wpart[w];
        g_partials[blockIdx.y * GX + blockIdx.x] = s;
        __threadfence();
        unsigned old = atomicAdd(&g_ticket, 1u);
        islast = (old == NBLK - 1);
    }
    __syncthreads();

    // Last block performs the final deterministic reduction
    if (islast) {
        __threadfence();
        double s = 0.0;
        for (int i = threadIdx.x; i < NBLK; i += 256) s += g_partials[i];
        smr[threadIdx.x] = s;
        __syncthreads();
        for (int off = 128; off > 0; off >>= 1) {
            if (threadIdx.x < off) smr[threadIdx.x] += smr[threadIdx.x + off];
            __syncthreads();
        }
        if (threadIdx.x == 0) {
            // x2: mirror-symmetric halves contribute identically; ALPHA = 1
            out[0] = (float)(smr[0] * 2.0 * (double)d * (double)d);
            g_ticket = 0;                           // reset for graph replay
        }
    }
}

extern "C" void kernel_launch(void* const* d_in, const int* in_sizes, int n_in,
                              void* d_out, int out_size) {
    const float* eps = (const float*)d_in[0];
    const float* gs  = (const float*)d_in[1];
    float* out = (float*)d_out;

    dim3 grid(GX, GY);       // 19 x 64 = 1216 blocks
    dim3 block(256);
    curve_kernel<<<grid, block>>>(eps, gs, out);
}